// round 2
// baseline (speedup 1.0000x reference)
#include <cuda_runtime.h>

// ---------------------------------------------------------------------------
// PCELayer: patch-routed mixture of conv experts + GroupNorm.  fp32 baseline.
//
// Shapes: x[8,64,128,128]; per expert e: W1[128,64,3,3], W2[128,128,3,3],
// Wr[128,64]; router MLP 80->128->8 on patch-pooled feats + fourier pos.
// out[8,128,128,128] fp32.
// ---------------------------------------------------------------------------

#define kB    8
#define kCIN  64
#define kCOUT 128
#define kH    128
#define kW    128
#define kE    8
#define kP    16
#define kHp   8
#define kWp   8
#define kF    4
#define kHID  128
#define kGCH  80
#define kG    8

// scratch (allocation-free contract: __device__ globals)
__device__ float g_h1[kB * kCOUT * kH * kW];          // 67 MB intermediate
__device__ float g_gates[kB * kHp * kWp * kE];        // router output
__device__ float g_stats[kB * kG * 2];                // groupnorm mean/rstd

// ---------------------------------------------------------------------------
// Router: one block per (b, hp, wp) patch.  128 threads.
// ---------------------------------------------------------------------------
__global__ void router_kernel(const float* __restrict__ x,
                              const float* __restrict__ Rw1,
                              const float* __restrict__ Rb1,
                              const float* __restrict__ Rw2,
                              const float* __restrict__ Rb2)
{
    __shared__ float s_g[kGCH];
    __shared__ float s_h[kHID];
    __shared__ float s_l[kE];

    const int blk = blockIdx.x;
    const int b  = blk >> 6;
    const int hp = (blk >> 3) & 7;
    const int wp = blk & 7;
    const int t  = threadIdx.x;

    if (t < 64) {
        // mean-pool channel t over the 16x16 patch
        const float* xp = x + ((b * kCIN + t) * kH + hp * kP) * kW + wp * kP;
        float s = 0.f;
        for (int r = 0; r < kP; r++) {
            const float4* rp = reinterpret_cast<const float4*>(xp + r * kW);
            #pragma unroll
            for (int c4 = 0; c4 < 4; c4++) {
                float4 v = rp[c4];
                s += v.x + v.y + v.z + v.w;
            }
        }
        s_g[t] = s * (1.f / 256.f);
    } else if (t < 80) {
        // fourier positional features: [sin(ay), cos(ay), sin(ax), cos(ax)] x 4 freqs
        int k = t - 64;
        int f = k & 3;
        int kind = k >> 2;
        float freq = (float)(1 << f) * 3.14159265358979323846f;
        float coord = (kind < 2) ? ((hp + 0.5f) / 8.0f) : ((wp + 0.5f) / 8.0f);
        float a = coord * freq;
        s_g[t] = (kind & 1) ? cosf(a) : sinf(a);
    }
    __syncthreads();

    // hidden layer: 128 units, each thread one unit
    {
        float hsum = Rb1[t];
        #pragma unroll 4
        for (int c = 0; c < kGCH; c++) hsum = fmaf(s_g[c], Rw1[c * kHID + t], hsum);
        s_h[t] = fmaxf(hsum, 0.f);
    }
    __syncthreads();

    if (t < kE) {
        float l = Rb2[t];
        #pragma unroll 4
        for (int d = 0; d < kHID; d++) l = fmaf(s_h[d], Rw2[d * kE + t], l);
        s_l[t] = l;
    }
    __syncthreads();

    if (t == 0) {
        float m = s_l[0];
        #pragma unroll
        for (int e = 1; e < kE; e++) m = fmaxf(m, s_l[e]);
        float ex[kE];
        float ssum = 0.f;
        #pragma unroll
        for (int e = 0; e < kE; e++) { ex[e] = expf(s_l[e] - m); ssum += ex[e]; }
        float inv = 1.f / ssum;
        #pragma unroll
        for (int e = 0; e < kE; e++)
            g_gates[((b * kHp + hp) * kWp + wp) * kE + e] = ex[e] * inv;
    }
}

// ---------------------------------------------------------------------------
// Conv building blocks.
// Block tile: 128 co x (32w x 4h) pixels. 256 threads.
// Thread: cg = t>>5 (co block of 16), pg = t&31 -> 4 consecutive x pixels.
// smem: s_in[8 ci][6 rows][pitch 35]  (rows 0..5 = y-1..y+4, cols 0..33 = x-1..x+32)
//       s_w [72 k][pitch 132]        (k = ci*9 + dy*3 + dx, 128 co)
// ---------------------------------------------------------------------------

#define IN_PITCH 35
#define W_PITCH  132

template <int CIN>
__device__ __forceinline__ void load_in_tile(float (&s_in)[8][6][IN_PITCH],
                                             const float* __restrict__ src,
                                             int b, int ci0, int gy0, int gx0, int t)
{
    for (int idx = t; idx < 8 * 6 * 34; idx += 256) {
        int ci  = idx / 204;
        int rem = idx - ci * 204;
        int row = rem / 34;
        int col = rem - row * 34;
        int gy = gy0 + row - 1;
        int gx = gx0 + col - 1;
        float v = 0.f;
        if ((unsigned)gy < (unsigned)kH && (unsigned)gx < (unsigned)kW)
            v = src[((b * CIN + ci0 + ci) * kH + gy) * kW + gx];
        s_in[ci][row][col] = v;
    }
}

template <int CIN>
__device__ __forceinline__ void load_w_chunk(float (&s_w)[72][W_PITCH],
                                             const float* __restrict__ W,
                                             int ci0, int t)
{
    // W layout [co][ci][3][3]; chunk of 8 ci -> 72 contiguous floats per co
    for (int idx = t; idx < 72 * 128; idx += 256) {
        int co = idx / 72;
        int kk = idx - co * 72;
        s_w[kk][co] = W[(co * CIN + ci0) * 9 + kk];
    }
}

__device__ __forceinline__ void load_in_center(float (&s_in)[8][6][IN_PITCH],
                                               const float* __restrict__ src,
                                               int b, int ci0, int gy0, int gx0, int t)
{
    for (int idx = t; idx < 8 * 4 * 32; idx += 256) {
        int ci  = idx >> 7;
        int rem = idx & 127;
        int row = rem >> 5;
        int col = rem & 31;
        s_in[ci][row][col] = src[((b * kCIN + ci0 + ci) * kH + gy0 + row) * kW + gx0 + col];
    }
}

__device__ __forceinline__ void load_wr_chunk(float (&s_w)[72][W_PITCH],
                                              const float* __restrict__ Wr,
                                              int ci0, int t)
{
    for (int idx = t; idx < 8 * 128; idx += 256) {
        int co = idx >> 3;
        int ci = idx & 7;
        s_w[ci][co] = Wr[co * kCIN + ci0 + ci];
    }
}

__device__ __forceinline__ void fma16x4(float acc[16][4], const float* wrow, int co0,
                                        float v0, float v1, float v2, float v3)
{
    const float4* wp = reinterpret_cast<const float4*>(wrow + co0);
    #pragma unroll
    for (int j4 = 0; j4 < 4; j4++) {
        float4 w4 = wp[j4];
        acc[j4 * 4 + 0][0] = fmaf(w4.x, v0, acc[j4 * 4 + 0][0]);
        acc[j4 * 4 + 0][1] = fmaf(w4.x, v1, acc[j4 * 4 + 0][1]);
        acc[j4 * 4 + 0][2] = fmaf(w4.x, v2, acc[j4 * 4 + 0][2]);
        acc[j4 * 4 + 0][3] = fmaf(w4.x, v3, acc[j4 * 4 + 0][3]);
        acc[j4 * 4 + 1][0] = fmaf(w4.y, v0, acc[j4 * 4 + 1][0]);
        acc[j4 * 4 + 1][1] = fmaf(w4.y, v1, acc[j4 * 4 + 1][1]);
        acc[j4 * 4 + 1][2] = fmaf(w4.y, v2, acc[j4 * 4 + 1][2]);
        acc[j4 * 4 + 1][3] = fmaf(w4.y, v3, acc[j4 * 4 + 1][3]);
        acc[j4 * 4 + 2][0] = fmaf(w4.z, v0, acc[j4 * 4 + 2][0]);
        acc[j4 * 4 + 2][1] = fmaf(w4.z, v1, acc[j4 * 4 + 2][1]);
        acc[j4 * 4 + 2][2] = fmaf(w4.z, v2, acc[j4 * 4 + 2][2]);
        acc[j4 * 4 + 2][3] = fmaf(w4.z, v3, acc[j4 * 4 + 2][3]);
        acc[j4 * 4 + 3][0] = fmaf(w4.w, v0, acc[j4 * 4 + 3][0]);
        acc[j4 * 4 + 3][1] = fmaf(w4.w, v1, acc[j4 * 4 + 3][1]);
        acc[j4 * 4 + 3][2] = fmaf(w4.w, v2, acc[j4 * 4 + 3][2]);
        acc[j4 * 4 + 3][3] = fmaf(w4.w, v3, acc[j4 * 4 + 3][3]);
    }
}

__device__ __forceinline__ void conv_chunk_mac(const float (&s_in)[8][6][IN_PITCH],
                                               const float (&s_w)[72][W_PITCH],
                                               int py, int px0, int co0, float acc[16][4])
{
    #pragma unroll 2
    for (int ci = 0; ci < 8; ci++) {
        #pragma unroll
        for (int dy = 0; dy < 3; dy++) {
            const float* rin = &s_in[ci][py + dy][px0];
            #pragma unroll
            for (int dx = 0; dx < 3; dx++) {
                int kk = ci * 9 + dy * 3 + dx;
                float v0 = rin[dx + 0];
                float v1 = rin[dx + 1];
                float v2 = rin[dx + 2];
                float v3 = rin[dx + 3];
                fma16x4(acc, s_w[kk], co0, v0, v1, v2, v3);
            }
        }
    }
}

__device__ __forceinline__ void res_chunk_mac(const float (&s_in)[8][6][IN_PITCH],
                                              const float (&s_w)[72][W_PITCH],
                                              int py, int px0, int co0, float acc[16][4])
{
    #pragma unroll 2
    for (int ci = 0; ci < 8; ci++) {
        const float* rin = &s_in[ci][py][px0];
        float v0 = rin[0];
        float v1 = rin[1];
        float v2 = rin[2];
        float v3 = rin[3];
        fma16x4(acc, s_w[ci], co0, v0, v1, v2, v3);
    }
}

// ---------------------------------------------------------------------------
// Stage 1 per expert: h1 = relu(conv3x3(x, W1) + b1)
// ---------------------------------------------------------------------------
__global__ void __launch_bounds__(256, 2)
conv1_kernel(const float* __restrict__ x, const float* __restrict__ W,
             const float* __restrict__ bias)
{
    __shared__ float s_in[8][6][IN_PITCH];
    __shared__ float s_w[72][W_PITCH];

    const int t = threadIdx.x;
    const int cg = t >> 5, pg = t & 31;
    const int co0 = cg * 16;
    const int px0 = (pg & 7) * 4, py = pg >> 3;
    const int gx0 = blockIdx.x * 32, gy0 = blockIdx.y * 4;
    const int b = blockIdx.z;

    float acc[16][4];
    #pragma unroll
    for (int j = 0; j < 16; j++)
        #pragma unroll
        for (int u = 0; u < 4; u++) acc[j][u] = 0.f;

    for (int ci0 = 0; ci0 < kCIN; ci0 += 8) {
        __syncthreads();
        load_in_tile<kCIN>(s_in, x, b, ci0, gy0, gx0, t);
        load_w_chunk<kCIN>(s_w, W, ci0, t);
        __syncthreads();
        conv_chunk_mac(s_in, s_w, py, px0, co0, acc);
    }

    const int gy = gy0 + py, gx = gx0 + px0;
    #pragma unroll
    for (int j = 0; j < 16; j++) {
        int co = co0 + j;
        float bb = bias[co];
        float4 o;
        o.x = fmaxf(acc[j][0] + bb, 0.f);
        o.y = fmaxf(acc[j][1] + bb, 0.f);
        o.z = fmaxf(acc[j][2] + bb, 0.f);
        o.w = fmaxf(acc[j][3] + bb, 0.f);
        *reinterpret_cast<float4*>(&g_h1[((b * kCOUT + co) * kH + gy) * kW + gx]) = o;
    }
}

// ---------------------------------------------------------------------------
// Stage 2 per expert: y += gate * relu(conv3x3(h1, W2) + 1x1(x, Wr) + b2 + br)
// ---------------------------------------------------------------------------
__global__ void __launch_bounds__(256, 2)
conv2_kernel(const float* __restrict__ x, const float* __restrict__ W2,
             const float* __restrict__ Wr, const float* __restrict__ b2,
             const float* __restrict__ br, int e, int is_first,
             float* __restrict__ out)
{
    __shared__ float s_in[8][6][IN_PITCH];
    __shared__ float s_w[72][W_PITCH];

    const int t = threadIdx.x;
    const int cg = t >> 5, pg = t & 31;
    const int co0 = cg * 16;
    const int px0 = (pg & 7) * 4, py = pg >> 3;
    const int gx0 = blockIdx.x * 32, gy0 = blockIdx.y * 4;
    const int b = blockIdx.z;

    float acc[16][4];
    #pragma unroll
    for (int j = 0; j < 16; j++)
        #pragma unroll
        for (int u = 0; u < 4; u++) acc[j][u] = 0.f;

    // main 3x3 conv over h1 (128 input channels)
    for (int ci0 = 0; ci0 < kCOUT; ci0 += 8) {
        __syncthreads();
        load_in_tile<kCOUT>(s_in, g_h1, b, ci0, gy0, gx0, t);
        load_w_chunk<kCOUT>(s_w, W2, ci0, t);
        __syncthreads();
        conv_chunk_mac(s_in, s_w, py, px0, co0, acc);
    }

    // 1x1 residual over x (64 input channels)
    for (int ci0 = 0; ci0 < kCIN; ci0 += 8) {
        __syncthreads();
        load_in_center(s_in, x, b, ci0, gy0, gx0, t);
        load_wr_chunk(s_w, Wr, ci0, t);
        __syncthreads();
        res_chunk_mac(s_in, s_w, py, px0, co0, acc);
    }

    const int gy = gy0 + py, gx = gx0 + px0;
    const int patch = (b * kHp + (gy >> 4)) * kWp + (gx >> 4);
    const float gate = g_gates[patch * kE + e];

    #pragma unroll
    for (int j = 0; j < 16; j++) {
        int co = co0 + j;
        float bb = b2[co] + br[co];
        float4 o;
        o.x = fmaxf(acc[j][0] + bb, 0.f) * gate;
        o.y = fmaxf(acc[j][1] + bb, 0.f) * gate;
        o.z = fmaxf(acc[j][2] + bb, 0.f) * gate;
        o.w = fmaxf(acc[j][3] + bb, 0.f) * gate;
        float4* op = reinterpret_cast<float4*>(&out[((b * kCOUT + co) * kH + gy) * kW + gx]);
        if (!is_first) {
            float4 prev = *op;
            o.x += prev.x; o.y += prev.y; o.z += prev.z; o.w += prev.w;
        }
        *op = o;
    }
}

// ---------------------------------------------------------------------------
// GroupNorm: reduce then apply.  One block per (b, g).
// ---------------------------------------------------------------------------
__global__ void gn_reduce_kernel(const float* __restrict__ y)
{
    const int bg = blockIdx.x;                       // b*8 + g
    const int t = threadIdx.x;
    const int N = (kCOUT / kG) * kH * kW;            // 262144 contiguous floats
    const float4* p = reinterpret_cast<const float4*>(y + (size_t)bg * N);

    double s = 0.0, sq = 0.0;
    for (int i = t; i < N / 4; i += 256) {
        float4 v = p[i];
        s  += (double)v.x + (double)v.y + (double)v.z + (double)v.w;
        sq += (double)v.x * v.x + (double)v.y * v.y +
              (double)v.z * v.z + (double)v.w * v.w;
    }
    __shared__ double sh_s[256];
    __shared__ double sh_q[256];
    sh_s[t] = s; sh_q[t] = sq;
    __syncthreads();
    for (int off = 128; off > 0; off >>= 1) {
        if (t < off) { sh_s[t] += sh_s[t + off]; sh_q[t] += sh_q[t + off]; }
        __syncthreads();
    }
    if (t == 0) {
        double mean = sh_s[0] / N;
        double var  = sh_q[0] / N - mean * mean;
        g_stats[bg * 2 + 0] = (float)mean;
        g_stats[bg * 2 + 1] = (float)(1.0 / sqrt(var + 1e-5));
    }
}

__global__ void gn_apply_kernel(float* __restrict__ y,
                                const float* __restrict__ gamma,
                                const float* __restrict__ beta)
{
    const int idx4 = blockIdx.x * 256 + threadIdx.x;
    const int idx = idx4 * 4;
    const int c = (idx >> 14) & 127;     // channel
    const int bg = idx >> 18;            // (b*128 + c) / 16 = b*8 + g
    const float mean = g_stats[bg * 2 + 0];
    const float rstd = g_stats[bg * 2 + 1];
    const float ga = gamma[c] * rstd;
    const float be = beta[c] - mean * ga;
    float4 v = *reinterpret_cast<float4*>(&y[idx]);
    v.x = v.x * ga + be;
    v.y = v.y * ga + be;
    v.z = v.z * ga + be;
    v.w = v.w * ga + be;
    *reinterpret_cast<float4*>(&y[idx]) = v;
}

// ---------------------------------------------------------------------------
// Launch
// ---------------------------------------------------------------------------
extern "C" void kernel_launch(void* const* d_in, const int* in_sizes, int n_in,
                              void* d_out, int out_size)
{
    const float* x     = (const float*)d_in[0];
    const float* W1    = (const float*)d_in[1];
    const float* b1    = (const float*)d_in[2];
    const float* W2    = (const float*)d_in[3];
    const float* b2    = (const float*)d_in[4];
    const float* Wr    = (const float*)d_in[5];
    const float* br    = (const float*)d_in[6];
    const float* Rw1   = (const float*)d_in[7];
    const float* Rb1   = (const float*)d_in[8];
    const float* Rw2   = (const float*)d_in[9];
    const float* Rb2   = (const float*)d_in[10];
    const float* gamma = (const float*)d_in[11];
    const float* beta  = (const float*)d_in[12];
    float* out = (float*)d_out;

    router_kernel<<<kB * kHp * kWp, 128>>>(x, Rw1, Rb1, Rw2, Rb2);

    dim3 grid(kW / 32, kH / 4, kB);  // (4, 32, 8)
    for (int e = 0; e < kE; e++) {
        conv1_kernel<<<grid, 256>>>(x,
                                    W1 + (size_t)e * kCOUT * kCIN * 9,
                                    b1 + e * kCOUT);
        conv2_kernel<<<grid, 256>>>(x,
                                    W2 + (size_t)e * kCOUT * kCOUT * 9,
                                    Wr + (size_t)e * kCOUT * kCIN,
                                    b2 + e * kCOUT,
                                    br + e * kCOUT,
                                    e, (e == 0) ? 1 : 0,
                                    out);
    }

    gn_reduce_kernel<<<kB * kG, 256>>>(out);
    gn_apply_kernel<<<(kB * kCOUT * kH * kW) / (256 * 4), 256>>>(out, gamma, beta);
}

// round 6
// speedup vs baseline: 2.1185x; 2.1185x over previous
#include <cuda_runtime.h>

// ---------------------------------------------------------------------------
// PCELayer on tensor cores: tf32 mma.sync implicit-GEMM convs + fused epilogues.
// R6 == R4 logic (infra retry #2). Change vs R4: no min-blocks launch_bounds
// (42KB smem -> 1 CTA/SM regardless; avoid the 128-reg cap / spill risk).
// ---------------------------------------------------------------------------

#define kB    8
#define kCIN  64
#define kCOUT 128
#define kH    128
#define kW    128
#define kE    8
#define kP    16
#define kHp   8
#define kWp   8
#define kHID  128
#define kGCH  80
#define kG    8

__device__ float g_h1[kB * kCOUT * kH * kW];
__device__ float g_gates[kB * kHp * kWp * kE];
__device__ float g_stats[kB * kG * 2];

// ---------------------------------------------------------------------------
// helpers
// ---------------------------------------------------------------------------
__device__ __forceinline__ unsigned f2tf(float f) {
    unsigned u;
    asm("cvt.rna.tf32.f32 %0, %1;" : "=r"(u) : "f"(f));
    return u;
}

__device__ __forceinline__ void mma_tf32(float acc[4], const unsigned a[4], const unsigned b[2]) {
    asm volatile(
        "mma.sync.aligned.m16n8k8.row.col.f32.tf32.tf32.f32 "
        "{%0,%1,%2,%3}, {%4,%5,%6,%7}, {%8,%9}, {%0,%1,%2,%3};\n"
        : "+f"(acc[0]), "+f"(acc[1]), "+f"(acc[2]), "+f"(acc[3])
        : "r"(a[0]), "r"(a[1]), "r"(a[2]), "r"(a[3]), "r"(b[0]), "r"(b[1]));
}

// ---------------------------------------------------------------------------
// Router
// ---------------------------------------------------------------------------
__global__ void router_kernel(const float* __restrict__ x,
                              const float* __restrict__ Rw1,
                              const float* __restrict__ Rb1,
                              const float* __restrict__ Rw2,
                              const float* __restrict__ Rb2)
{
    __shared__ float s_g[kGCH];
    __shared__ float s_h[kHID];
    __shared__ float s_l[kE];

    const int blk = blockIdx.x;
    const int b  = blk >> 6;
    const int hp = (blk >> 3) & 7;
    const int wp = blk & 7;
    const int t  = threadIdx.x;

    if (t < 64) {
        const float* xp = x + ((b * kCIN + t) * kH + hp * kP) * kW + wp * kP;
        float s = 0.f;
        for (int r = 0; r < kP; r++) {
            const float4* rp = reinterpret_cast<const float4*>(xp + r * kW);
            #pragma unroll
            for (int c4 = 0; c4 < 4; c4++) {
                float4 v = rp[c4];
                s += v.x + v.y + v.z + v.w;
            }
        }
        s_g[t] = s * (1.f / 256.f);
    } else if (t < 80) {
        int k = t - 64;
        int f = k & 3;
        int kind = k >> 2;
        float freq = (float)(1 << f) * 3.14159265358979323846f;
        float coord = (kind < 2) ? ((hp + 0.5f) / 8.0f) : ((wp + 0.5f) / 8.0f);
        float a = coord * freq;
        s_g[t] = (kind & 1) ? cosf(a) : sinf(a);
    }
    __syncthreads();

    {
        float hsum = Rb1[t];
        #pragma unroll 4
        for (int c = 0; c < kGCH; c++) hsum = fmaf(s_g[c], Rw1[c * kHID + t], hsum);
        s_h[t] = fmaxf(hsum, 0.f);
    }
    __syncthreads();

    if (t < kE) {
        float l = Rb2[t];
        #pragma unroll 4
        for (int d = 0; d < kHID; d++) l = fmaf(s_h[d], Rw2[d * kE + t], l);
        s_l[t] = l;
    }
    __syncthreads();

    if (t == 0) {
        float m = s_l[0];
        #pragma unroll
        for (int e = 1; e < kE; e++) m = fmaxf(m, s_l[e]);
        float ex[kE];
        float ssum = 0.f;
        #pragma unroll
        for (int e = 0; e < kE; e++) { ex[e] = expf(s_l[e] - m); ssum += ex[e]; }
        float inv = 1.f / ssum;
        #pragma unroll
        for (int e = 0; e < kE; e++)
            g_gates[((b * kHp + hp) * kWp + wp) * kE + e] = ex[e] * inv;
    }
}

// ---------------------------------------------------------------------------
// Tensor-core conv tile machinery.
// CTA: 128 co x (32w x 2h) pixels, 256 threads = 8 warps.
// warp w: wm = w>>1 -> co group of 32;  wy = w&1 -> y row.
// smem: s_in[8 ci][4 rows][34], s_w[128 co][76].
// ---------------------------------------------------------------------------

struct ConvSmem {
    unsigned s_in[8][4][34];
    unsigned s_w[128][76];
};

template <int CIN>
__device__ __forceinline__ void stage_in(ConvSmem& sm, const float* __restrict__ src,
                                         int b, int ci0, int gy0, int gx0, int t)
{
    for (int idx = t; idx < 8 * 4 * 34; idx += 256) {
        int ci  = idx / 136;
        int rem = idx - ci * 136;
        int row = rem / 34;
        int col = rem - row * 34;
        int gy = gy0 + row - 1;
        int gx = gx0 + col - 1;
        float v = 0.f;
        if ((unsigned)gy < (unsigned)kH && (unsigned)gx < (unsigned)kW)
            v = src[((b * CIN + ci0 + ci) * kH + gy) * kW + gx];
        sm.s_in[ci][row][col] = f2tf(v);
    }
}

template <int CIN>
__device__ __forceinline__ void stage_w(ConvSmem& sm, const float* __restrict__ W,
                                        int ci0, int t)
{
    for (int idx = t; idx < 128 * 72; idx += 256) {
        int co = idx / 72;
        int kk = idx - co * 72;
        sm.s_w[co][kk] = f2tf(W[(co * CIN + ci0) * 9 + kk]);
    }
}

__device__ __forceinline__ void stage_wr(ConvSmem& sm, const float* __restrict__ Wr,
                                         int ci0, int t)
{
    for (int idx = t; idx < 128 * 8; idx += 256) {
        int co = idx >> 3;
        int ci = idx & 7;
        sm.s_w[co][ci] = f2tf(Wr[co * kCIN + ci0 + ci]);
    }
}

__device__ __forceinline__ void chunk_mma3x3(ConvSmem& sm, int wm, int wy, int g, int tin,
                                             float acc[2][4][4])
{
    #pragma unroll
    for (int dyx = 0; dyx < 9; dyx++) {
        const int dy = dyx / 3, dx = dyx % 3;
        unsigned a[2][4], bf[4][2];
        #pragma unroll
        for (int mt = 0; mt < 2; mt++) {
            int co = wm * 32 + mt * 16 + g;
            a[mt][0] = sm.s_w[co    ][tin * 9 + dyx];
            a[mt][1] = sm.s_w[co + 8][tin * 9 + dyx];
            a[mt][2] = sm.s_w[co    ][(tin + 4) * 9 + dyx];
            a[mt][3] = sm.s_w[co + 8][(tin + 4) * 9 + dyx];
        }
        const int row = wy + dy;
        #pragma unroll
        for (int nt = 0; nt < 4; nt++) {
            int col = nt * 8 + g + dx;
            bf[nt][0] = sm.s_in[tin    ][row][col];
            bf[nt][1] = sm.s_in[tin + 4][row][col];
        }
        #pragma unroll
        for (int mt = 0; mt < 2; mt++)
            #pragma unroll
            for (int nt = 0; nt < 4; nt++)
                mma_tf32(acc[mt][nt], a[mt], bf[nt]);
    }
}

__device__ __forceinline__ void chunk_mma1x1(ConvSmem& sm, int wm, int wy, int g, int tin,
                                             float acc[2][4][4])
{
    unsigned a[2][4], bf[4][2];
    #pragma unroll
    for (int mt = 0; mt < 2; mt++) {
        int co = wm * 32 + mt * 16 + g;
        a[mt][0] = sm.s_w[co    ][tin];
        a[mt][1] = sm.s_w[co + 8][tin];
        a[mt][2] = sm.s_w[co    ][tin + 4];
        a[mt][3] = sm.s_w[co + 8][tin + 4];
    }
    const int row = wy + 1;
    #pragma unroll
    for (int nt = 0; nt < 4; nt++) {
        int col = nt * 8 + g + 1;
        bf[nt][0] = sm.s_in[tin    ][row][col];
        bf[nt][1] = sm.s_in[tin + 4][row][col];
    }
    #pragma unroll
    for (int mt = 0; mt < 2; mt++)
        #pragma unroll
        for (int nt = 0; nt < 4; nt++)
            mma_tf32(acc[mt][nt], a[mt], bf[nt]);
}

// ---------------------------------------------------------------------------
// Stage 1: h1 = relu(conv3x3(x, W1) + b1)
// ---------------------------------------------------------------------------
__global__ void __launch_bounds__(256)
conv1_tc(const float* __restrict__ x, const float* __restrict__ W,
         const float* __restrict__ bias)
{
    __shared__ ConvSmem sm;

    const int t = threadIdx.x;
    const int l = t & 31, w = t >> 5;
    const int g = l >> 2, tin = l & 3;
    const int wm = w >> 1, wy = w & 1;
    const int gx0 = blockIdx.x * 32, gy0 = blockIdx.y * 2;
    const int b = blockIdx.z;

    float acc[2][4][4];
    #pragma unroll
    for (int mt = 0; mt < 2; mt++)
        #pragma unroll
        for (int nt = 0; nt < 4; nt++)
            #pragma unroll
            for (int u = 0; u < 4; u++) acc[mt][nt][u] = 0.f;

    for (int ci0 = 0; ci0 < kCIN; ci0 += 8) {
        __syncthreads();
        stage_in<kCIN>(sm, x, b, ci0, gy0, gx0, t);
        stage_w<kCIN>(sm, W, ci0, t);
        __syncthreads();
        chunk_mma3x3(sm, wm, wy, g, tin, acc);
    }

    const int y = gy0 + wy;
    #pragma unroll
    for (int mt = 0; mt < 2; mt++) {
        int co0 = wm * 32 + mt * 16 + g;
        float bb0 = bias[co0], bb1 = bias[co0 + 8];
        #pragma unroll
        for (int nt = 0; nt < 4; nt++) {
            int gx = gx0 + nt * 8 + tin * 2;
            float2 o0, o1;
            o0.x = fmaxf(acc[mt][nt][0] + bb0, 0.f);
            o0.y = fmaxf(acc[mt][nt][1] + bb0, 0.f);
            o1.x = fmaxf(acc[mt][nt][2] + bb1, 0.f);
            o1.y = fmaxf(acc[mt][nt][3] + bb1, 0.f);
            *reinterpret_cast<float2*>(&g_h1[((b * kCOUT + co0    ) * kH + y) * kW + gx]) = o0;
            *reinterpret_cast<float2*>(&g_h1[((b * kCOUT + co0 + 8) * kH + y) * kW + gx]) = o1;
        }
    }
}

// ---------------------------------------------------------------------------
// Stage 2: out (+)= gate * relu(conv3x3(h1, W2) + 1x1(x, Wr) + b2 + br)
// ---------------------------------------------------------------------------
__global__ void __launch_bounds__(256)
conv2_tc(const float* __restrict__ x, const float* __restrict__ W2,
         const float* __restrict__ Wr, const float* __restrict__ b2,
         const float* __restrict__ br, int e, int is_first,
         float* __restrict__ out)
{
    __shared__ ConvSmem sm;

    const int t = threadIdx.x;
    const int l = t & 31, w = t >> 5;
    const int g = l >> 2, tin = l & 3;
    const int wm = w >> 1, wy = w & 1;
    const int gx0 = blockIdx.x * 32, gy0 = blockIdx.y * 2;
    const int b = blockIdx.z;

    float acc[2][4][4];
    #pragma unroll
    for (int mt = 0; mt < 2; mt++)
        #pragma unroll
        for (int nt = 0; nt < 4; nt++)
            #pragma unroll
            for (int u = 0; u < 4; u++) acc[mt][nt][u] = 0.f;

    // 3x3 conv over h1 (128 ci)
    for (int ci0 = 0; ci0 < kCOUT; ci0 += 8) {
        __syncthreads();
        stage_in<kCOUT>(sm, g_h1, b, ci0, gy0, gx0, t);
        stage_w<kCOUT>(sm, W2, ci0, t);
        __syncthreads();
        chunk_mma3x3(sm, wm, wy, g, tin, acc);
    }

    // 1x1 residual over x (64 ci)
    for (int ci0 = 0; ci0 < kCIN; ci0 += 8) {
        __syncthreads();
        stage_in<kCIN>(sm, x, b, ci0, gy0, gx0, t);
        stage_wr(sm, Wr, ci0, t);
        __syncthreads();
        chunk_mma1x1(sm, wm, wy, g, tin, acc);
    }

    const int y = gy0 + wy;
    // CTA spans 32 px in x = TWO 16-px router patches. nt tiles 0,1 -> left
    // patch; nt tiles 2,3 -> right patch.
    const int prow = (b * kHp + (y >> 4)) * kWp;
    const float gateL = g_gates[(prow + ((gx0      ) >> 4)) * kE + e];
    const float gateR = g_gates[(prow + ((gx0 + 16) >> 4)) * kE + e];

    #pragma unroll
    for (int mt = 0; mt < 2; mt++) {
        int co0 = wm * 32 + mt * 16 + g;
        float bb0 = b2[co0] + br[co0];
        float bb1 = b2[co0 + 8] + br[co0 + 8];
        #pragma unroll
        for (int nt = 0; nt < 4; nt++) {
            const float gate = (nt < 2) ? gateL : gateR;
            int gx = gx0 + nt * 8 + tin * 2;
            float2 o0, o1;
            o0.x = fmaxf(acc[mt][nt][0] + bb0, 0.f) * gate;
            o0.y = fmaxf(acc[mt][nt][1] + bb0, 0.f) * gate;
            o1.x = fmaxf(acc[mt][nt][2] + bb1, 0.f) * gate;
            o1.y = fmaxf(acc[mt][nt][3] + bb1, 0.f) * gate;
            float2* p0 = reinterpret_cast<float2*>(&out[((b * kCOUT + co0    ) * kH + y) * kW + gx]);
            float2* p1 = reinterpret_cast<float2*>(&out[((b * kCOUT + co0 + 8) * kH + y) * kW + gx]);
            if (!is_first) {
                float2 v0 = *p0, v1 = *p1;
                o0.x += v0.x; o0.y += v0.y;
                o1.x += v1.x; o1.y += v1.y;
            }
            *p0 = o0;
            *p1 = o1;
        }
    }
}

// ---------------------------------------------------------------------------
// GroupNorm
// ---------------------------------------------------------------------------
__global__ void gn_reduce_kernel(const float* __restrict__ y)
{
    const int bg = blockIdx.x;
    const int t = threadIdx.x;
    const int N = (kCOUT / kG) * kH * kW;
    const float4* p = reinterpret_cast<const float4*>(y + (size_t)bg * N);

    double s = 0.0, sq = 0.0;
    for (int i = t; i < N / 4; i += 256) {
        float4 v = p[i];
        s  += (double)v.x + (double)v.y + (double)v.z + (double)v.w;
        sq += (double)v.x * v.x + (double)v.y * v.y +
              (double)v.z * v.z + (double)v.w * v.w;
    }
    __shared__ double sh_s[256];
    __shared__ double sh_q[256];
    sh_s[t] = s; sh_q[t] = sq;
    __syncthreads();
    for (int off = 128; off > 0; off >>= 1) {
        if (t < off) { sh_s[t] += sh_s[t + off]; sh_q[t] += sh_q[t + off]; }
        __syncthreads();
    }
    if (t == 0) {
        double mean = sh_s[0] / N;
        double var  = sh_q[0] / N - mean * mean;
        g_stats[bg * 2 + 0] = (float)mean;
        g_stats[bg * 2 + 1] = (float)(1.0 / sqrt(var + 1e-5));
    }
}

__global__ void gn_apply_kernel(float* __restrict__ y,
                                const float* __restrict__ gamma,
                                const float* __restrict__ beta)
{
    const int idx4 = blockIdx.x * 256 + threadIdx.x;
    const int idx = idx4 * 4;
    const int c = (idx >> 14) & 127;
    const int bg = idx >> 18;
    const float mean = g_stats[bg * 2 + 0];
    const float rstd = g_stats[bg * 2 + 1];
    const float ga = gamma[c] * rstd;
    const float be = beta[c] - mean * ga;
    float4 v = *reinterpret_cast<float4*>(&y[idx]);
    v.x = v.x * ga + be;
    v.y = v.y * ga + be;
    v.z = v.z * ga + be;
    v.w = v.w * ga + be;
    *reinterpret_cast<float4*>(&y[idx]) = v;
}

// ---------------------------------------------------------------------------
// Launch
// ---------------------------------------------------------------------------
extern "C" void kernel_launch(void* const* d_in, const int* in_sizes, int n_in,
                              void* d_out, int out_size)
{
    const float* x     = (const float*)d_in[0];
    const float* W1    = (const float*)d_in[1];
    const float* b1    = (const float*)d_in[2];
    const float* W2    = (const float*)d_in[3];
    const float* b2    = (const float*)d_in[4];
    const float* Wr    = (const float*)d_in[5];
    const float* br    = (const float*)d_in[6];
    const float* Rw1   = (const float*)d_in[7];
    const float* Rb1   = (const float*)d_in[8];
    const float* Rw2   = (const float*)d_in[9];
    const float* Rb2   = (const float*)d_in[10];
    const float* gamma = (const float*)d_in[11];
    const float* beta  = (const float*)d_in[12];
    float* out = (float*)d_out;

    router_kernel<<<kB * kHp * kWp, 128>>>(x, Rw1, Rb1, Rw2, Rb2);

    dim3 grid(kW / 32, kH / 2, kB);  // (4, 64, 8) = 2048 CTAs
    for (int e = 0; e < kE; e++) {
        conv1_tc<<<grid, 256>>>(x,
                                W1 + (size_t)e * kCOUT * kCIN * 9,
                                b1 + e * kCOUT);
        conv2_tc<<<grid, 256>>>(x,
                                W2 + (size_t)e * kCOUT * kCOUT * 9,
                                Wr + (size_t)e * kCOUT * kCIN,
                                b2 + e * kCOUT,
                                br + e * kCOUT,
                                e, (e == 0) ? 1 : 0,
                                out);
    }

    gn_reduce_kernel<<<kB * kG, 256>>>(out);
    gn_apply_kernel<<<(kB * kCOUT * kH * kW) / (256 * 4), 256>>>(out, gamma, beta);
}

// round 7
// speedup vs baseline: 3.6184x; 1.7080x over previous
#include <cuda_runtime.h>

// ---------------------------------------------------------------------------
// PCELayer R7: tf32 mma.sync implicit-GEMM convs with
//  - pre-rounded/pre-permuted weights+inputs (no cvt / no permute in hot loop)
//  - cp.async double-buffered staging pipeline
//  - A-fragments as single LDS.128
//  - split GroupNorm reduction
// ---------------------------------------------------------------------------

#define kB    8
#define kCIN  64
#define kCOUT 128
#define kH    128
#define kW    128
#define kE    8
#define kP    16
#define kHp   8
#define kWp   8
#define kHID  128
#define kGCH  80
#define kG    8

// scratch
__device__ float    g_h1[kB * kCOUT * kH * kW];        // conv1 out (tf32-rounded)
__device__ float    g_xtf[kB * kCIN * kH * kW];        // x, tf32-rounded
__device__ unsigned g_W1p[kE * kCIN * 9 * 128];        // permuted W1
__device__ unsigned g_W2p[kE * kCOUT * 9 * 128];       // permuted W2
__device__ unsigned g_Wrp[kE * (kCIN / 8) * 1024];     // permuted Wr
__device__ float    g_gates[kB * kHp * kWp * kE];
__device__ double   g_part[kB * kG * 32 * 2];
__device__ float    g_stats[kB * kG * 2];

// ---------------------------------------------------------------------------
// helpers
// ---------------------------------------------------------------------------
__device__ __forceinline__ unsigned f2tf(float f) {
    unsigned u;
    asm("cvt.rna.tf32.f32 %0, %1;" : "=r"(u) : "f"(f));
    return u;
}

__device__ __forceinline__ void mma_tf32(float acc[4], unsigned a0, unsigned a1,
                                         unsigned a2, unsigned a3,
                                         unsigned b0, unsigned b1) {
    asm volatile(
        "mma.sync.aligned.m16n8k8.row.col.f32.tf32.tf32.f32 "
        "{%0,%1,%2,%3}, {%4,%5,%6,%7}, {%8,%9}, {%0,%1,%2,%3};\n"
        : "+f"(acc[0]), "+f"(acc[1]), "+f"(acc[2]), "+f"(acc[3])
        : "r"(a0), "r"(a1), "r"(a2), "r"(a3), "r"(b0), "r"(b1));
}

__device__ __forceinline__ void cp_async16(unsigned* dst, const void* src) {
    unsigned d = (unsigned)__cvta_generic_to_shared(dst);
    asm volatile("cp.async.cg.shared.global [%0], [%1], 16;" :: "r"(d), "l"(src));
}
__device__ __forceinline__ void cp_async4z(unsigned* dst, const void* src, bool ok) {
    unsigned d = (unsigned)__cvta_generic_to_shared(dst);
    int sz = ok ? 4 : 0;
    asm volatile("cp.async.ca.shared.global [%0], [%1], 4, %2;" :: "r"(d), "l"(src), "r"(sz));
}
__device__ __forceinline__ void cp_commit() {
    asm volatile("cp.async.commit_group;");
}
template <int N>
__device__ __forceinline__ void cp_wait() {
    asm volatile("cp.async.wait_group %0;" :: "n"(N));
}

// ---------------------------------------------------------------------------
// Prep kernels: round + permute into scratch.
// Permuted 3x3 layout per expert: [chunk(CIN/8)][tap 9][ct 8][lane 32][j 4]
//   co = ct*16 + (lane>>2) + (j&1)*8 ; ci = chunk*8 + (lane&3) + (j>>1)*4
// ---------------------------------------------------------------------------
__global__ void prep_x_kernel(const float* __restrict__ x) {
    int idx = blockIdx.x * 256 + threadIdx.x;          // float4 index
    const float4* in = reinterpret_cast<const float4*>(x);
    float4 v = in[idx];
    float4 o;
    o.x = __uint_as_float(f2tf(v.x));
    o.y = __uint_as_float(f2tf(v.y));
    o.z = __uint_as_float(f2tf(v.z));
    o.w = __uint_as_float(f2tf(v.w));
    reinterpret_cast<float4*>(g_xtf)[idx] = o;
}

__global__ void prep_w3x3_kernel(const float* __restrict__ W, unsigned* __restrict__ out,
                                 int CIN, int total) {
    int perE = CIN * 1152;                             // CIN/8 chunks * 9216
    for (int idx = blockIdx.x * 256 + threadIdx.x; idx < total; idx += gridDim.x * 256) {
        int e = idx / perE;
        int r = idx - e * perE;
        int chunk = r / 9216;
        int r2 = r - chunk * 9216;
        int tap = r2 >> 10;
        int r3 = r2 & 1023;
        int ct = r3 >> 7;
        int lane = (r3 >> 2) & 31;
        int j = r3 & 3;
        int co = ct * 16 + (lane >> 2) + (j & 1) * 8;
        int ci = chunk * 8 + (lane & 3) + (j >> 1) * 4;
        out[idx] = f2tf(W[((size_t)(e * 128 + co) * CIN + ci) * 9 + tap]);
    }
}

__global__ void prep_wr_kernel(const float* __restrict__ Wr) {
    int total = kE * 8192;
    for (int idx = blockIdx.x * 256 + threadIdx.x; idx < total; idx += gridDim.x * 256) {
        int e = idx >> 13;
        int r = idx & 8191;
        int chunk = r >> 10;
        int r3 = r & 1023;
        int ct = r3 >> 7;
        int lane = (r3 >> 2) & 31;
        int j = r3 & 3;
        int co = ct * 16 + (lane >> 2) + (j & 1) * 8;
        int ci = chunk * 8 + (lane & 3) + (j >> 1) * 4;
        g_Wrp[idx] = f2tf(Wr[(e * 128 + co) * kCIN + ci]);
    }
}

// ---------------------------------------------------------------------------
// Router (unchanged)
// ---------------------------------------------------------------------------
__global__ void router_kernel(const float* __restrict__ x,
                              const float* __restrict__ Rw1,
                              const float* __restrict__ Rb1,
                              const float* __restrict__ Rw2,
                              const float* __restrict__ Rb2)
{
    __shared__ float s_g[kGCH];
    __shared__ float s_h[kHID];
    __shared__ float s_l[kE];

    const int blk = blockIdx.x;
    const int b  = blk >> 6;
    const int hp = (blk >> 3) & 7;
    const int wp = blk & 7;
    const int t  = threadIdx.x;

    if (t < 64) {
        const float* xp = x + ((b * kCIN + t) * kH + hp * kP) * kW + wp * kP;
        float s = 0.f;
        for (int r = 0; r < kP; r++) {
            const float4* rp = reinterpret_cast<const float4*>(xp + r * kW);
            #pragma unroll
            for (int c4 = 0; c4 < 4; c4++) {
                float4 v = rp[c4];
                s += v.x + v.y + v.z + v.w;
            }
        }
        s_g[t] = s * (1.f / 256.f);
    } else if (t < 80) {
        int k = t - 64;
        int f = k & 3;
        int kind = k >> 2;
        float freq = (float)(1 << f) * 3.14159265358979323846f;
        float coord = (kind < 2) ? ((hp + 0.5f) / 8.0f) : ((wp + 0.5f) / 8.0f);
        float a = coord * freq;
        s_g[t] = (kind & 1) ? cosf(a) : sinf(a);
    }
    __syncthreads();

    {
        float hsum = Rb1[t];
        #pragma unroll 4
        for (int c = 0; c < kGCH; c++) hsum = fmaf(s_g[c], Rw1[c * kHID + t], hsum);
        s_h[t] = fmaxf(hsum, 0.f);
    }
    __syncthreads();

    if (t < kE) {
        float l = Rb2[t];
        #pragma unroll 4
        for (int d = 0; d < kHID; d++) l = fmaf(s_h[d], Rw2[d * kE + t], l);
        s_l[t] = l;
    }
    __syncthreads();

    if (t == 0) {
        float m = s_l[0];
        #pragma unroll
        for (int e = 1; e < kE; e++) m = fmaxf(m, s_l[e]);
        float ex[kE];
        float ssum = 0.f;
        #pragma unroll
        for (int e = 0; e < kE; e++) { ex[e] = expf(s_l[e] - m); ssum += ex[e]; }
        float inv = 1.f / ssum;
        #pragma unroll
        for (int e = 0; e < kE; e++)
            g_gates[((b * kHp + hp) * kWp + wp) * kE + e] = ex[e] * inv;
    }
}

// ---------------------------------------------------------------------------
// Conv kernel (pipelined, double-buffered).
// CTA: 128 co x (32w x 2h) px, 256 threads = 8 warps; warp wm=w>>1, wy=w&1.
// Per buffer: w[9216] (permuted A frags) + in[8][4][34] (halo tile).
// ---------------------------------------------------------------------------
#define W_WORDS   9216
#define IN_WORDS  1088
#define BUF_WORDS (W_WORDS + IN_WORDS)    // 10304 words = 41216 B

template <int NMAIN, bool C2>
__global__ void __launch_bounds__(256)
conv_tc(const float* __restrict__ smain,     // main conv input (xtf or h1)
        const unsigned* __restrict__ wmain,  // permuted main weights (expert base)
        const unsigned* __restrict__ wres,   // permuted residual weights (expert base)
        const float* __restrict__ bias,      // b1 / b2
        const float* __restrict__ bias2,     // br (C2 only)
        int e, int is_first, float* __restrict__ out)
{
    extern __shared__ unsigned dyn[];

    const int t = threadIdx.x;
    const int lane = t & 31, w = t >> 5;
    const int g = lane >> 2, tin = lane & 3;
    const int wm = w >> 1, wy = w & 1;
    const int gx0 = blockIdx.x * 32, gy0 = blockIdx.y * 2;
    const int b = blockIdx.z;

    const int CINM = NMAIN * 8;
    const int njobs = NMAIN + (C2 ? kCIN / 8 : 0);

    // -------- staging --------
    auto issue = [&](int job, int bufi) {
        unsigned* bw  = dyn + bufi * BUF_WORDS;
        unsigned* bin = bw + W_WORDS;
        const float* src; int ci0, cin_src; const unsigned* wsrc; int wn;
        if (job < NMAIN) {
            src = smain; ci0 = job * 8; cin_src = CINM;
            wsrc = wmain + job * W_WORDS; wn = W_WORDS;
        } else {
            src = g_xtf; ci0 = (job - NMAIN) * 8; cin_src = kCIN;
            wsrc = wres + (job - NMAIN) * 1024; wn = 1024;
        }
        // weights: contiguous 16B copies
        for (int i = t; i < wn / 4; i += 256)
            cp_async16(bw + i * 4, wsrc + i * 4);
        // input halo tile: 4B copies with zero-fill for OOB
        for (int idx = t; idx < IN_WORDS; idx += 256) {
            int ci  = idx / 136;
            int rem = idx - ci * 136;
            int row = rem / 34;
            int col = rem - row * 34;
            int gy = gy0 + row - 1;
            int gx = gx0 + col - 1;
            bool ok = ((unsigned)gy < (unsigned)kH) && ((unsigned)gx < (unsigned)kW);
            const float* sp = ok
                ? src + ((size_t)(b * cin_src + ci0 + ci) * kH + gy) * kW + gx
                : src;
            cp_async4z(bin + idx, sp, ok);
        }
        cp_commit();
    };

    // -------- compute --------
    float acc[2][4][4];
    #pragma unroll
    for (int mt = 0; mt < 2; mt++)
        #pragma unroll
        for (int nt = 0; nt < 4; nt++)
            #pragma unroll
            for (int u = 0; u < 4; u++) acc[mt][nt][u] = 0.f;

    auto do_mma = [&](int job, int bufi) {
        unsigned* bw = dyn + bufi * BUF_WORDS;
        const uint4* aw = reinterpret_cast<const uint4*>(bw);
        const unsigned (*sin)[4][34] =
            reinterpret_cast<const unsigned (*)[4][34]>(bw + W_WORDS);
        if (job < NMAIN) {
            #pragma unroll
            for (int tap = 0; tap < 9; tap++) {
                const int dy = tap / 3, dx = tap % 3;
                uint4 A0 = aw[(tap * 8 + 2 * wm    ) * 32 + lane];
                uint4 A1 = aw[(tap * 8 + 2 * wm + 1) * 32 + lane];
                const int row = wy + dy;
                unsigned b0[4], b1[4];
                #pragma unroll
                for (int nt = 0; nt < 4; nt++) {
                    int col = nt * 8 + g + dx;
                    b0[nt] = sin[tin    ][row][col];
                    b1[nt] = sin[tin + 4][row][col];
                }
                #pragma unroll
                for (int nt = 0; nt < 4; nt++) {
                    mma_tf32(acc[0][nt], A0.x, A0.y, A0.z, A0.w, b0[nt], b1[nt]);
                    mma_tf32(acc[1][nt], A1.x, A1.y, A1.z, A1.w, b0[nt], b1[nt]);
                }
            }
        } else {
            uint4 A0 = aw[(2 * wm    ) * 32 + lane];
            uint4 A1 = aw[(2 * wm + 1) * 32 + lane];
            const int row = wy + 1;
            #pragma unroll
            for (int nt = 0; nt < 4; nt++) {
                int col = nt * 8 + g + 1;
                unsigned b0 = sin[tin    ][row][col];
                unsigned b1 = sin[tin + 4][row][col];
                mma_tf32(acc[0][nt], A0.x, A0.y, A0.z, A0.w, b0, b1);
                mma_tf32(acc[1][nt], A1.x, A1.y, A1.z, A1.w, b0, b1);
            }
        }
    };

    // -------- pipeline --------
    issue(0, 0);
    for (int j = 0; j < njobs; j++) {
        if (j + 1 < njobs) {
            issue(j + 1, (j + 1) & 1);
            cp_wait<1>();
        } else {
            cp_wait<0>();
        }
        __syncthreads();
        do_mma(j, j & 1);
        __syncthreads();
    }

    // -------- epilogue --------
    const int y = gy0 + wy;
    if (!C2) {
        #pragma unroll
        for (int mt = 0; mt < 2; mt++) {
            int co0 = wm * 32 + mt * 16 + g;
            float bb0 = bias[co0], bb1 = bias[co0 + 8];
            #pragma unroll
            for (int nt = 0; nt < 4; nt++) {
                int gx = gx0 + nt * 8 + tin * 2;
                float2 o0, o1;
                o0.x = __uint_as_float(f2tf(fmaxf(acc[mt][nt][0] + bb0, 0.f)));
                o0.y = __uint_as_float(f2tf(fmaxf(acc[mt][nt][1] + bb0, 0.f)));
                o1.x = __uint_as_float(f2tf(fmaxf(acc[mt][nt][2] + bb1, 0.f)));
                o1.y = __uint_as_float(f2tf(fmaxf(acc[mt][nt][3] + bb1, 0.f)));
                *reinterpret_cast<float2*>(&g_h1[((b * kCOUT + co0    ) * kH + y) * kW + gx]) = o0;
                *reinterpret_cast<float2*>(&g_h1[((b * kCOUT + co0 + 8) * kH + y) * kW + gx]) = o1;
            }
        }
    } else {
        const int prow = (b * kHp + (y >> 4)) * kWp;
        const float gateL = g_gates[(prow + ((gx0      ) >> 4)) * kE + e];
        const float gateR = g_gates[(prow + ((gx0 + 16) >> 4)) * kE + e];
        #pragma unroll
        for (int mt = 0; mt < 2; mt++) {
            int co0 = wm * 32 + mt * 16 + g;
            float bb0 = bias[co0] + bias2[co0];
            float bb1 = bias[co0 + 8] + bias2[co0 + 8];
            #pragma unroll
            for (int nt = 0; nt < 4; nt++) {
                const float gate = (nt < 2) ? gateL : gateR;
                int gx = gx0 + nt * 8 + tin * 2;
                float2 o0, o1;
                o0.x = fmaxf(acc[mt][nt][0] + bb0, 0.f) * gate;
                o0.y = fmaxf(acc[mt][nt][1] + bb0, 0.f) * gate;
                o1.x = fmaxf(acc[mt][nt][2] + bb1, 0.f) * gate;
                o1.y = fmaxf(acc[mt][nt][3] + bb1, 0.f) * gate;
                float2* p0 = reinterpret_cast<float2*>(&out[((b * kCOUT + co0    ) * kH + y) * kW + gx]);
                float2* p1 = reinterpret_cast<float2*>(&out[((b * kCOUT + co0 + 8) * kH + y) * kW + gx]);
                if (!is_first) {
                    float2 v0 = *p0, v1 = *p1;
                    o0.x += v0.x; o0.y += v0.y;
                    o1.x += v1.x; o1.y += v1.y;
                }
                *p0 = o0;
                *p1 = o1;
            }
        }
    }
}

// ---------------------------------------------------------------------------
// GroupNorm: two-stage reduce + apply
// ---------------------------------------------------------------------------
__global__ void gn_partial_kernel(const float* __restrict__ y)
{
    const int bid = blockIdx.x;           // 512 = 64bg * ... actually kB*kG*32
    const int bg = bid >> 5, sl = bid & 31;
    const int t = threadIdx.x;
    const float4* p = reinterpret_cast<const float4*>(
        y + (size_t)bg * ((kCOUT / kG) * kH * kW) + sl * 8192);

    double s = 0.0, q = 0.0;
    for (int i = t; i < 2048; i += 256) {
        float4 v = p[i];
        s += (double)v.x + (double)v.y + (double)v.z + (double)v.w;
        q += (double)v.x * v.x + (double)v.y * v.y +
             (double)v.z * v.z + (double)v.w * v.w;
    }
    __shared__ double sh_s[256], sh_q[256];
    sh_s[t] = s; sh_q[t] = q;
    __syncthreads();
    for (int off = 128; off > 0; off >>= 1) {
        if (t < off) { sh_s[t] += sh_s[t + off]; sh_q[t] += sh_q[t + off]; }
        __syncthreads();
    }
    if (t == 0) {
        g_part[(bg * 32 + sl) * 2 + 0] = sh_s[0];
        g_part[(bg * 32 + sl) * 2 + 1] = sh_q[0];
    }
}

__global__ void gn_final_kernel()
{
    const int bg = blockIdx.x;
    const int t = threadIdx.x;           // 32 threads
    double s = g_part[(bg * 32 + t) * 2 + 0];
    double q = g_part[(bg * 32 + t) * 2 + 1];
    #pragma unroll
    for (int off = 16; off > 0; off >>= 1) {
        s += __shfl_down_sync(0xffffffffu, s, off);
        q += __shfl_down_sync(0xffffffffu, q, off);
    }
    if (t == 0) {
        const double N = (double)((kCOUT / kG) * kH * kW);
        double mean = s / N;
        double var  = q / N - mean * mean;
        g_stats[bg * 2 + 0] = (float)mean;
        g_stats[bg * 2 + 1] = (float)(1.0 / sqrt(var + 1e-5));
    }
}

__global__ void gn_apply_kernel(float* __restrict__ y,
                                const float* __restrict__ gamma,
                                const float* __restrict__ beta)
{
    const int idx4 = blockIdx.x * 256 + threadIdx.x;
    const int idx = idx4 * 4;
    const int c = (idx >> 14) & 127;
    const int bg = idx >> 18;
    const float mean = g_stats[bg * 2 + 0];
    const float rstd = g_stats[bg * 2 + 1];
    const float ga = gamma[c] * rstd;
    const float be = beta[c] - mean * ga;
    float4 v = *reinterpret_cast<float4*>(&y[idx]);
    v.x = v.x * ga + be;
    v.y = v.y * ga + be;
    v.z = v.z * ga + be;
    v.w = v.w * ga + be;
    *reinterpret_cast<float4*>(&y[idx]) = v;
}

// ---------------------------------------------------------------------------
// Launch
// ---------------------------------------------------------------------------
extern "C" void kernel_launch(void* const* d_in, const int* in_sizes, int n_in,
                              void* d_out, int out_size)
{
    const float* x     = (const float*)d_in[0];
    const float* W1    = (const float*)d_in[1];
    const float* b1    = (const float*)d_in[2];
    const float* W2    = (const float*)d_in[3];
    const float* b2    = (const float*)d_in[4];
    const float* Wr    = (const float*)d_in[5];
    const float* br    = (const float*)d_in[6];
    const float* Rw1   = (const float*)d_in[7];
    const float* Rb1   = (const float*)d_in[8];
    const float* Rw2   = (const float*)d_in[9];
    const float* Rb2   = (const float*)d_in[10];
    const float* gamma = (const float*)d_in[11];
    const float* beta  = (const float*)d_in[12];
    float* out = (float*)d_out;

    const int smem_bytes = 2 * BUF_WORDS * 4;   // 82432

    static int configured = -1;
    // (Safe under graph capture: attribute set is host-side, idempotent.)
    cudaFuncSetAttribute(conv_tc<8, false>,
                         cudaFuncAttributeMaxDynamicSharedMemorySize, smem_bytes);
    cudaFuncSetAttribute(conv_tc<16, true>,
                         cudaFuncAttributeMaxDynamicSharedMemorySize, smem_bytes);
    (void)configured;

    // prep
    prep_x_kernel<<<(kB * kCIN * kH * kW) / (256 * 4), 256>>>(x);
    {
        unsigned* w1p; cudaGetSymbolAddress((void**)&w1p, g_W1p);
        unsigned* w2p; cudaGetSymbolAddress((void**)&w2p, g_W2p);
        prep_w3x3_kernel<<<1024, 256>>>(W1, w1p, kCIN,  kE * kCIN  * 9 * 128);
        prep_w3x3_kernel<<<1024, 256>>>(W2, w2p, kCOUT, kE * kCOUT * 9 * 128);
        prep_wr_kernel<<<256, 256>>>(Wr);
    }
    router_kernel<<<kB * kHp * kWp, 128>>>(x, Rw1, Rb1, Rw2, Rb2);

    unsigned* w1p; cudaGetSymbolAddress((void**)&w1p, g_W1p);
    unsigned* w2p; cudaGetSymbolAddress((void**)&w2p, g_W2p);
    unsigned* wrp; cudaGetSymbolAddress((void**)&wrp, g_Wrp);
    float* xtf;    cudaGetSymbolAddress((void**)&xtf, g_xtf);
    float* h1;     cudaGetSymbolAddress((void**)&h1, g_h1);

    dim3 grid(kW / 32, kH / 2, kB);  // 2048 CTAs
    for (int e = 0; e < kE; e++) {
        conv_tc<8, false><<<grid, 256, smem_bytes>>>(
            xtf, w1p + (size_t)e * kCIN * 9 * 128, nullptr,
            b1 + e * kCOUT, nullptr, e, 0, nullptr);
        conv_tc<16, true><<<grid, 256, smem_bytes>>>(
            h1, w2p + (size_t)e * kCOUT * 9 * 128, wrp + (size_t)e * 8192,
            b2 + e * kCOUT, br + e * kCOUT, e, (e == 0) ? 1 : 0, out);
    }

    gn_partial_kernel<<<kB * kG * 32, 256>>>(out);
    gn_final_kernel<<<kB * kG, 32>>>();
    gn_apply_kernel<<<(kB * kCOUT * kH * kW) / (256 * 4), 256>>>(out, gamma, beta);
}